// round 3
// baseline (speedup 1.0000x reference)
#include <cuda_runtime.h>
#include <cstdint>

// Problem constants
#define BATCH 256
#define TT    512
#define DIN   128
#define DFEAT 256
#define DLAT  512
#define GG    2048          // 4*DLAT
#define NBLK  128           // persistent grid: 4 (row tiles) x 32 (latent tiles)
#define ENC_SLOTS 32        // enc ring slots (power of 2)

// ---------------- small device-global scratch (~9 MB total) ----------------
__device__ float g_encbuf[ENC_SLOTS][BATCH * DFEAT]; // 8 MB: enc time-slice ring
__device__ float g_hbuf[2][BATCH * DLAT];            // 1 MB: ping-pong h
__device__ unsigned g_bar_cnt;
__device__ unsigned g_bar_gen;

// ---------------- math helpers ----------------
__device__ __forceinline__ float sigmoidf_(float x) {
    return 1.0f / (1.0f + __expf(-x));
}
__device__ __forceinline__ float tanhf_(float x) {
    x = fminf(fmaxf(x, -12.0f), 12.0f);
    float e = __expf(2.0f * x);
    return (e - 1.0f) / (e + 1.0f);
}

// ---------------- grid-wide barrier (all NBLK blocks co-resident) ----------------
__device__ __forceinline__ void grid_sync(unsigned* gen) {
    __syncthreads();
    if (threadIdx.x == 0) {
        __threadfence();
        unsigned arrived = atomicAdd(&g_bar_cnt, 1u);
        if (arrived == NBLK - 1) {
            atomicExch(&g_bar_cnt, 0u);
            __threadfence();
            *((volatile unsigned*)&g_bar_gen) = *gen + 1u;
        } else {
            while (*((volatile unsigned*)&g_bar_gen) == *gen) { __nanosleep(64); }
        }
        __threadfence();
    }
    __syncthreads();
    (*gen)++;
}

// ---------------- smem layout (floats) ----------------
#define SM_WS   0                       // [512][64]  W_h slice
#define SM_HA   (SM_WS + 512*64)        // [16][68]   A^T staging (shared by all phases)
#define SM_SB   (SM_HA + 16*68)         // [16][64]   B staging (phases E, X)
#define SM_XZ0  (SM_SB + 16*64)         // [64][65]   xz ping
#define SM_XZ1  (SM_XZ0 + 64*65)        // [64][65]   xz pong
#define SM_CS   (SM_XZ1 + 64*65)        // [64][16]   cell state
#define SMEM_FLOATS (SM_CS + 64*16)     // 44224 floats = 176,896 B

// Phase E: one 64x64 tile of enc for an 8-step batch.
// Work matrix: [8*256 rows, 256 cols] = x(batch,time slice) @ W_enc, tanh+bias.
__device__ __forceinline__ void enc_batch(
    const float* __restrict__ x, const float* __restrict__ W_enc,
    const float* __restrict__ b_enc, float* hA, float* sB,
    int s_base, int bid, int tid)
{
    const int q = bid >> 2;
    const int s = s_base + (q >> 2);
    if (s >= TT) return;
    const int b0  = (q & 3) * 64;
    const int n0e = (bid & 3) * 64;
    const int tn = tid & 15, tm = tid >> 4;

    float acc[8][4];
#pragma unroll
    for (int i = 0; i < 8; i++)
#pragma unroll
        for (int j = 0; j < 4; j++) acc[i][j] = 0.0f;

#pragma unroll 1
    for (int k0 = 0; k0 < DIN; k0 += 16) {
#pragma unroll
        for (int q2 = 0; q2 < 2; q2++) {              // A^T tile: x rows
            int f = tid * 2 + q2;
            int row = f >> 2, kq = f & 3;
            float4 v = *reinterpret_cast<const float4*>(
                &x[(size_t)(b0 + row) * TT * DIN + (size_t)s * DIN + k0 + kq * 4]);
            hA[(kq * 4 + 0) * 68 + row] = v.x; hA[(kq * 4 + 1) * 68 + row] = v.y;
            hA[(kq * 4 + 2) * 68 + row] = v.z; hA[(kq * 4 + 3) * 68 + row] = v.w;
        }
#pragma unroll
        for (int q2 = 0; q2 < 2; q2++) {              // B tile: W_enc
            int f = tid * 2 + q2;
            int kr = f >> 4, nq = f & 15;
            float4 v = *reinterpret_cast<const float4*>(
                &W_enc[(size_t)(k0 + kr) * DFEAT + n0e + nq * 4]);
            *reinterpret_cast<float4*>(&sB[kr * 64 + nq * 4]) = v;
        }
        __syncthreads();
#pragma unroll
        for (int k = 0; k < 16; k++) {
            float a[8], b[4];
            *reinterpret_cast<float4*>(&a[0]) = *reinterpret_cast<const float4*>(&hA[k * 68 + tm * 8]);
            *reinterpret_cast<float4*>(&a[4]) = *reinterpret_cast<const float4*>(&hA[k * 68 + tm * 8 + 4]);
            *reinterpret_cast<float4*>(&b[0]) = *reinterpret_cast<const float4*>(&sB[k * 64 + tn * 4]);
#pragma unroll
            for (int i = 0; i < 8; i++)
#pragma unroll
                for (int j = 0; j < 4; j++) acc[i][j] = fmaf(a[i], b[j], acc[i][j]);
        }
        __syncthreads();
    }

    float bia[4];
    *reinterpret_cast<float4*>(&bia[0]) = *reinterpret_cast<const float4*>(&b_enc[n0e + tn * 4]);
    float* dst = g_encbuf[s & (ENC_SLOTS - 1)];
#pragma unroll
    for (int i = 0; i < 8; i++) {
        float4 v4;
        v4.x = tanhf_(acc[i][0] + bia[0]);
        v4.y = tanhf_(acc[i][1] + bia[1]);
        v4.z = tanhf_(acc[i][2] + bia[2]);
        v4.w = tanhf_(acc[i][3] + bia[3]);
        *reinterpret_cast<float4*>(&dst[(size_t)(b0 + tm * 8 + i) * DFEAT + n0e + tn * 4]) = v4;
    }
}

// Phase X: this block's xz slice for timestep s, into smem xzdst [64][65].
// xz = enc[s][m0:m0+64, :] @ W_x[:, 64 gate-cols of (jb)] + b_lstm
__device__ __forceinline__ void xz_phase(
    const float* __restrict__ W_x, const float* __restrict__ b_lstm,
    float* hA, float* sB, float* xzdst,
    int s, int m0, int j0, int tid)
{
    const int tn = tid & 15, tm = tid >> 4;
    const float* encp = g_encbuf[s & (ENC_SLOTS - 1)];

    float acc[8][4];
#pragma unroll
    for (int i = 0; i < 8; i++)
#pragma unroll
        for (int j = 0; j < 4; j++) acc[i][j] = 0.0f;

#pragma unroll 1
    for (int k0 = 0; k0 < DFEAT; k0 += 16) {
#pragma unroll
        for (int q2 = 0; q2 < 2; q2++) {              // A^T tile: enc rows
            int f = tid * 2 + q2;
            int row = f >> 2, kq = f & 3;
            float4 v = *reinterpret_cast<const float4*>(
                &encp[(size_t)(m0 + row) * DFEAT + k0 + kq * 4]);
            hA[(kq * 4 + 0) * 68 + row] = v.x; hA[(kq * 4 + 1) * 68 + row] = v.y;
            hA[(kq * 4 + 2) * 68 + row] = v.z; hA[(kq * 4 + 3) * 68 + row] = v.w;
        }
#pragma unroll
        for (int q2 = 0; q2 < 2; q2++) {              // B tile: W_x gate-cols
            int f = tid * 2 + q2;
            int kr = f >> 4, nq = f & 15;
            int gcol = (nq >> 2) * DLAT + j0 + (nq & 3) * 4;
            float4 v = *reinterpret_cast<const float4*>(&W_x[(size_t)(k0 + kr) * GG + gcol]);
            *reinterpret_cast<float4*>(&sB[kr * 64 + nq * 4]) = v;
        }
        __syncthreads();
#pragma unroll
        for (int k = 0; k < 16; k++) {
            float a[8], b[4];
            *reinterpret_cast<float4*>(&a[0]) = *reinterpret_cast<const float4*>(&hA[k * 68 + tm * 8]);
            *reinterpret_cast<float4*>(&a[4]) = *reinterpret_cast<const float4*>(&hA[k * 68 + tm * 8 + 4]);
            *reinterpret_cast<float4*>(&b[0]) = *reinterpret_cast<const float4*>(&sB[k * 64 + tn * 4]);
#pragma unroll
            for (int i = 0; i < 8; i++)
#pragma unroll
                for (int j = 0; j < 4; j++) acc[i][j] = fmaf(a[i], b[j], acc[i][j]);
        }
        __syncthreads();
    }

    float bia[4];
    *reinterpret_cast<float4*>(&bia[0]) = *reinterpret_cast<const float4*>(
        &b_lstm[(tn >> 2) * DLAT + j0 + (tn & 3) * 4]);
#pragma unroll
    for (int i = 0; i < 8; i++)
#pragma unroll
        for (int j = 0; j < 4; j++)
            xzdst[(tm * 8 + i) * 65 + tn * 4 + j] = acc[i][j] + bia[j];
}

// ---------------- the single persistent kernel ----------------
__global__ void __launch_bounds__(128, 1) lstm_fused_kernel(
    const float* __restrict__ x, const float* __restrict__ W_enc,
    const float* __restrict__ b_enc, const float* __restrict__ W_x,
    const float* __restrict__ W_h, const float* __restrict__ b_lstm,
    const float* __restrict__ W_dec, const float* __restrict__ b_dec,
    float* __restrict__ out)
{
    extern __shared__ float smem[];
    float* Ws  = smem + SM_WS;
    float* hA  = smem + SM_HA;
    float* sB  = smem + SM_SB;
    float* xzP[2] = { smem + SM_XZ0, smem + SM_XZ1 };
    float* cS  = smem + SM_CS;

    const int tid = threadIdx.x;
    const int bid = blockIdx.x;
    const int jb = bid & 31;             // latent col tile (16 wide)
    const int mb = bid >> 5;             // batch row tile (64 rows)
    const int m0 = mb * 64, j0 = jb * 16;
    const int tn = tid & 15, tm = tid >> 4;

    // ---- init: W_h slice (gate-aligned), c=0, h0=0 ----
    for (int idx = tid; idx < 512 * 64; idx += 128) {
        int k = idx >> 6, c = idx & 63;
        Ws[idx] = W_h[(size_t)k * GG + (c >> 4) * DLAT + j0 + (c & 15)];
    }
    for (int idx = tid; idx < 64 * 16; idx += 128) cS[idx] = 0.0f;
    for (int idx = tid; idx < 64 * 16; idx += 128)
        g_hbuf[0][(m0 + (idx >> 4)) * DLAT + j0 + (idx & 15)] = 0.0f;

    unsigned gen = *((volatile unsigned*)&g_bar_gen);

    // ---- prologue: enc for s in [0,16), then xz_0 ----
    enc_batch(x, W_enc, b_enc, hA, sB, 0, bid, tid);
    enc_batch(x, W_enc, b_enc, hA, sB, 8, bid, tid);
    grid_sync(&gen);                                   // publish enc[0..16) and h0
    xz_phase(W_x, b_lstm, hA, sB, xzP[0], 0, m0, j0, tid);
    __syncthreads();                                   // xz_0 visible block-wide

    // ---- main scan ----
#pragma unroll 1
    for (int t = 0; t < TT; t++) {
        if ((t & 7) == 0 && t + 16 < TT)
            enc_batch(x, W_enc, b_enc, hA, sB, t + 16, bid, tid);
        if (t + 1 < TT)
            xz_phase(W_x, b_lstm, hA, sB, xzP[(t + 1) & 1], t + 1, m0, j0, tid);

        const float* hb = g_hbuf[t & 1];
        float* hn = g_hbuf[(t + 1) & 1];
        float* zS = xzP[t & 1];

        // acc init from this block's xz slice (each thread reads its own cells)
        float acc[8][4];
#pragma unroll
        for (int i = 0; i < 8; i++)
#pragma unroll
            for (int j = 0; j < 4; j++)
                acc[i][j] = zS[(tm * 8 + i) * 65 + tn * 4 + j];

        // z += h_prev @ Ws   (K = 512, chunks of 16)
#pragma unroll 1
        for (int kc = 0; kc < DLAT; kc += 16) {
#pragma unroll
            for (int q2 = 0; q2 < 2; q2++) {
                int f = tid * 2 + q2;
                int m = f >> 2, qq = f & 3;
                float4 v = *reinterpret_cast<const float4*>(&hb[(m0 + m) * DLAT + kc + qq * 4]);
                hA[(qq * 4 + 0) * 68 + m] = v.x; hA[(qq * 4 + 1) * 68 + m] = v.y;
                hA[(qq * 4 + 2) * 68 + m] = v.z; hA[(qq * 4 + 3) * 68 + m] = v.w;
            }
            __syncthreads();
#pragma unroll
            for (int k = 0; k < 16; k++) {
                float a[8], b[4];
                *reinterpret_cast<float4*>(&a[0]) = *reinterpret_cast<const float4*>(&hA[k * 68 + tm * 8]);
                *reinterpret_cast<float4*>(&a[4]) = *reinterpret_cast<const float4*>(&hA[k * 68 + tm * 8 + 4]);
                *reinterpret_cast<float4*>(&b[0]) = *reinterpret_cast<const float4*>(&Ws[(kc + k) * 64 + tn * 4]);
#pragma unroll
                for (int i = 0; i < 8; i++)
#pragma unroll
                    for (int j = 0; j < 4; j++) acc[i][j] = fmaf(a[i], b[j], acc[i][j]);
            }
            __syncthreads();
        }

        // stage z back into the (now-consumed) xz slot for gate-gather
#pragma unroll
        for (int i = 0; i < 8; i++)
#pragma unroll
            for (int j = 0; j < 4; j++)
                zS[(tm * 8 + i) * 65 + tn * 4 + j] = acc[i][j];
        __syncthreads();

        // gates + state update: 1024 cells / 128 threads
#pragma unroll
        for (int it = 0; it < 8; it++) {
            int m = (tid >> 4) + it * 8;
            int j = tid & 15;
            float zi = zS[m * 65 + j];
            float zf = zS[m * 65 + 16 + j];
            float zg = zS[m * 65 + 32 + j];
            float zo = zS[m * 65 + 48 + j];
            float ig = sigmoidf_(zi);
            float fg = sigmoidf_(zf);
            float gg = tanhf_(zg);
            float og = sigmoidf_(zo);
            float cn = fg * cS[m * 16 + j] + ig * gg;
            cS[m * 16 + j] = cn;
            hn[(m0 + m) * DLAT + j0 + j] = og * tanhf_(cn);
        }
        grid_sync(&gen);
    }

    // decoder: out[b] = h_last @ W_dec + b_dec  (h_last in buf[TT&1] = buf[0])
    if (jb == 0 && tid < 64) {
        int row = m0 + tid;
        const float* hf = g_hbuf[0];
        float s = 0.0f;
        for (int k = 0; k < DLAT; k++) s = fmaf(hf[row * DLAT + k], W_dec[k], s);
        out[row] = s + b_dec[0];
    }
}

// ---------------- eager touch (harmless; materializes module early if possible) ----
namespace {
struct EagerLoad {
    EagerLoad() {
        void* p;
        cudaGetSymbolAddress(&p, g_encbuf);
        cudaGetSymbolAddress(&p, g_hbuf);
        cudaGetSymbolAddress(&p, g_bar_cnt);
        cudaGetSymbolAddress(&p, g_bar_gen);
        cudaFuncSetAttribute(lstm_fused_kernel,
                             cudaFuncAttributeMaxDynamicSharedMemorySize,
                             SMEM_FLOATS * (int)sizeof(float));
    }
};
EagerLoad eager_load_instance;
}  // namespace

// ---------------- launch ----------------
extern "C" void kernel_launch(void* const* d_in, const int* in_sizes, int n_in,
                              void* d_out, int out_size)
{
    const float* x      = (const float*)d_in[0];
    const float* W_enc  = (const float*)d_in[1];
    const float* b_enc  = (const float*)d_in[2];
    const float* W_x    = (const float*)d_in[3];
    const float* W_h    = (const float*)d_in[4];
    const float* b_lstm = (const float*)d_in[5];
    const float* W_dec  = (const float*)d_in[6];
    const float* b_dec  = (const float*)d_in[7];
    float* out = (float*)d_out;

    cudaFuncSetAttribute(lstm_fused_kernel,
                         cudaFuncAttributeMaxDynamicSharedMemorySize,
                         SMEM_FLOATS * (int)sizeof(float));

    lstm_fused_kernel<<<NBLK, 128, SMEM_FLOATS * (int)sizeof(float)>>>(
        x, W_enc, b_enc, W_x, W_h, b_lstm, W_dec, b_dec, out);
}

// round 4
// speedup vs baseline: 1.0012x; 1.0012x over previous
#include <cuda_runtime.h>
#include <cstdint>

// Problem constants
#define BATCH 256
#define TT    512
#define DIN   128
#define DFEAT 256
#define DLAT  512
#define GG    2048          // 4*DLAT
#define NBLK  128           // persistent grid: 4 (row tiles) x 32 (latent tiles)
#define ENC_SLOTS 32        // enc ring slots (power of 2)

// ---------------- small device-global scratch (~9 MB total) ----------------
__device__ float g_encbuf[ENC_SLOTS][BATCH * DFEAT]; // 8 MB: enc time-slice ring
__device__ float g_hbuf[2][BATCH * DLAT];            // 1 MB: ping-pong h
__device__ unsigned g_bar_cnt;
__device__ unsigned g_bar_gen;

// ---------------- math helpers ----------------
__device__ __forceinline__ float sigmoidf_(float x) {
    return 1.0f / (1.0f + __expf(-x));
}
__device__ __forceinline__ float tanhf_(float x) {
    x = fminf(fmaxf(x, -12.0f), 12.0f);
    float e = __expf(2.0f * x);
    return (e - 1.0f) / (e + 1.0f);
}

// ---------------- grid-wide barrier (all NBLK blocks co-resident) ----------------
__device__ __forceinline__ void grid_sync(unsigned* gen) {
    __syncthreads();
    if (threadIdx.x == 0) {
        __threadfence();
        unsigned arrived = atomicAdd(&g_bar_cnt, 1u);
        if (arrived == NBLK - 1) {
            atomicExch(&g_bar_cnt, 0u);
            __threadfence();
            *((volatile unsigned*)&g_bar_gen) = *gen + 1u;
        } else {
            while (*((volatile unsigned*)&g_bar_gen) == *gen) { __nanosleep(64); }
        }
        __threadfence();
    }
    __syncthreads();
    (*gen)++;
}

// ---------------- smem layout (floats) ----------------
#define SM_WS   0                       // [512][64]  W_h slice
#define SM_HA   (SM_WS + 512*64)        // [16][68]   A^T staging (shared by all phases)
#define SM_SB   (SM_HA + 16*68)         // [16][64]   B staging (phases E, X)
#define SM_XZ0  (SM_SB + 16*64)         // [64][65]   xz ping
#define SM_XZ1  (SM_XZ0 + 64*65)        // [64][65]   xz pong
#define SM_CS   (SM_XZ1 + 64*65)        // [64][16]   cell state
#define SMEM_FLOATS (SM_CS + 64*16)     // 44224 floats = 176,896 B

// Phase E: one 64x64 tile of enc for an 8-step batch.
// Work matrix: [8*256 rows, 256 cols] = x(batch,time slice) @ W_enc, tanh+bias.
__device__ __forceinline__ void enc_batch(
    const float* __restrict__ x, const float* __restrict__ W_enc,
    const float* __restrict__ b_enc, float* hA, float* sB,
    int s_base, int bid, int tid)
{
    const int q = bid >> 2;
    const int s = s_base + (q >> 2);
    if (s >= TT) return;
    const int b0  = (q & 3) * 64;
    const int n0e = (bid & 3) * 64;
    const int tn = tid & 15, tm = tid >> 4;

    float acc[8][4];
#pragma unroll
    for (int i = 0; i < 8; i++)
#pragma unroll
        for (int j = 0; j < 4; j++) acc[i][j] = 0.0f;

#pragma unroll 1
    for (int k0 = 0; k0 < DIN; k0 += 16) {
#pragma unroll
        for (int q2 = 0; q2 < 2; q2++) {              // A^T tile: x rows
            int f = tid * 2 + q2;
            int row = f >> 2, kq = f & 3;
            float4 v = *reinterpret_cast<const float4*>(
                &x[(size_t)(b0 + row) * TT * DIN + (size_t)s * DIN + k0 + kq * 4]);
            hA[(kq * 4 + 0) * 68 + row] = v.x; hA[(kq * 4 + 1) * 68 + row] = v.y;
            hA[(kq * 4 + 2) * 68 + row] = v.z; hA[(kq * 4 + 3) * 68 + row] = v.w;
        }
#pragma unroll
        for (int q2 = 0; q2 < 2; q2++) {              // B tile: W_enc
            int f = tid * 2 + q2;
            int kr = f >> 4, nq = f & 15;
            float4 v = *reinterpret_cast<const float4*>(
                &W_enc[(size_t)(k0 + kr) * DFEAT + n0e + nq * 4]);
            *reinterpret_cast<float4*>(&sB[kr * 64 + nq * 4]) = v;
        }
        __syncthreads();
#pragma unroll
        for (int k = 0; k < 16; k++) {
            float a[8], b[4];
            *reinterpret_cast<float4*>(&a[0]) = *reinterpret_cast<const float4*>(&hA[k * 68 + tm * 8]);
            *reinterpret_cast<float4*>(&a[4]) = *reinterpret_cast<const float4*>(&hA[k * 68 + tm * 8 + 4]);
            *reinterpret_cast<float4*>(&b[0]) = *reinterpret_cast<const float4*>(&sB[k * 64 + tn * 4]);
#pragma unroll
            for (int i = 0; i < 8; i++)
#pragma unroll
                for (int j = 0; j < 4; j++) acc[i][j] = fmaf(a[i], b[j], acc[i][j]);
        }
        __syncthreads();
    }

    float bia[4];
    *reinterpret_cast<float4*>(&bia[0]) = *reinterpret_cast<const float4*>(&b_enc[n0e + tn * 4]);
    float* dst = g_encbuf[s & (ENC_SLOTS - 1)];
#pragma unroll
    for (int i = 0; i < 8; i++) {
        float4 v4;
        v4.x = tanhf_(acc[i][0] + bia[0]);
        v4.y = tanhf_(acc[i][1] + bia[1]);
        v4.z = tanhf_(acc[i][2] + bia[2]);
        v4.w = tanhf_(acc[i][3] + bia[3]);
        *reinterpret_cast<float4*>(&dst[(size_t)(b0 + tm * 8 + i) * DFEAT + n0e + tn * 4]) = v4;
    }
}

// Phase X: this block's xz slice for timestep s, into smem xzdst [64][65].
// xz = enc[s][m0:m0+64, :] @ W_x[:, 64 gate-cols of (jb)] + b_lstm
__device__ __forceinline__ void xz_phase(
    const float* __restrict__ W_x, const float* __restrict__ b_lstm,
    float* hA, float* sB, float* xzdst,
    int s, int m0, int j0, int tid)
{
    const int tn = tid & 15, tm = tid >> 4;
    const float* encp = g_encbuf[s & (ENC_SLOTS - 1)];

    float acc[8][4];
#pragma unroll
    for (int i = 0; i < 8; i++)
#pragma unroll
        for (int j = 0; j < 4; j++) acc[i][j] = 0.0f;

#pragma unroll 1
    for (int k0 = 0; k0 < DFEAT; k0 += 16) {
#pragma unroll
        for (int q2 = 0; q2 < 2; q2++) {              // A^T tile: enc rows
            int f = tid * 2 + q2;
            int row = f >> 2, kq = f & 3;
            float4 v = *reinterpret_cast<const float4*>(
                &encp[(size_t)(m0 + row) * DFEAT + k0 + kq * 4]);
            hA[(kq * 4 + 0) * 68 + row] = v.x; hA[(kq * 4 + 1) * 68 + row] = v.y;
            hA[(kq * 4 + 2) * 68 + row] = v.z; hA[(kq * 4 + 3) * 68 + row] = v.w;
        }
#pragma unroll
        for (int q2 = 0; q2 < 2; q2++) {              // B tile: W_x gate-cols
            int f = tid * 2 + q2;
            int kr = f >> 4, nq = f & 15;
            int gcol = (nq >> 2) * DLAT + j0 + (nq & 3) * 4;
            float4 v = *reinterpret_cast<const float4*>(&W_x[(size_t)(k0 + kr) * GG + gcol]);
            *reinterpret_cast<float4*>(&sB[kr * 64 + nq * 4]) = v;
        }
        __syncthreads();
#pragma unroll
        for (int k = 0; k < 16; k++) {
            float a[8], b[4];
            *reinterpret_cast<float4*>(&a[0]) = *reinterpret_cast<const float4*>(&hA[k * 68 + tm * 8]);
            *reinterpret_cast<float4*>(&a[4]) = *reinterpret_cast<const float4*>(&hA[k * 68 + tm * 8 + 4]);
            *reinterpret_cast<float4*>(&b[0]) = *reinterpret_cast<const float4*>(&sB[k * 64 + tn * 4]);
#pragma unroll
            for (int i = 0; i < 8; i++)
#pragma unroll
                for (int j = 0; j < 4; j++) acc[i][j] = fmaf(a[i], b[j], acc[i][j]);
        }
        __syncthreads();
    }

    float bia[4];
    *reinterpret_cast<float4*>(&bia[0]) = *reinterpret_cast<const float4*>(
        &b_lstm[(tn >> 2) * DLAT + j0 + (tn & 3) * 4]);
#pragma unroll
    for (int i = 0; i < 8; i++)
#pragma unroll
        for (int j = 0; j < 4; j++)
            xzdst[(tm * 8 + i) * 65 + tn * 4 + j] = acc[i][j] + bia[j];
}

// ---------------- the single persistent kernel ----------------
__global__ void __launch_bounds__(128, 1) lstm_fused_kernel(
    const float* __restrict__ x, const float* __restrict__ W_enc,
    const float* __restrict__ b_enc, const float* __restrict__ W_x,
    const float* __restrict__ W_h, const float* __restrict__ b_lstm,
    const float* __restrict__ W_dec, const float* __restrict__ b_dec,
    float* __restrict__ out)
{
    extern __shared__ float smem[];
    float* Ws  = smem + SM_WS;
    float* hA  = smem + SM_HA;
    float* sB  = smem + SM_SB;
    float* xzP[2] = { smem + SM_XZ0, smem + SM_XZ1 };
    float* cS  = smem + SM_CS;

    const int tid = threadIdx.x;
    const int bid = blockIdx.x;
    const int jb = bid & 31;             // latent col tile (16 wide)
    const int mb = bid >> 5;             // batch row tile (64 rows)
    const int m0 = mb * 64, j0 = jb * 16;
    const int tn = tid & 15, tm = tid >> 4;

    // ---- init: W_h slice (gate-aligned), c=0, h0=0 ----
    for (int idx = tid; idx < 512 * 64; idx += 128) {
        int k = idx >> 6, c = idx & 63;
        Ws[idx] = W_h[(size_t)k * GG + (c >> 4) * DLAT + j0 + (c & 15)];
    }
    for (int idx = tid; idx < 64 * 16; idx += 128) cS[idx] = 0.0f;
    for (int idx = tid; idx < 64 * 16; idx += 128)
        g_hbuf[0][(m0 + (idx >> 4)) * DLAT + j0 + (idx & 15)] = 0.0f;

    unsigned gen = *((volatile unsigned*)&g_bar_gen);

    // ---- prologue: enc for s in [0,16), then xz_0 ----
    enc_batch(x, W_enc, b_enc, hA, sB, 0, bid, tid);
    enc_batch(x, W_enc, b_enc, hA, sB, 8, bid, tid);
    grid_sync(&gen);                                   // publish enc[0..16) and h0
    xz_phase(W_x, b_lstm, hA, sB, xzP[0], 0, m0, j0, tid);
    __syncthreads();                                   // xz_0 visible block-wide

    // ---- main scan ----
#pragma unroll 1
    for (int t = 0; t < TT; t++) {
        if ((t & 7) == 0 && t + 16 < TT)
            enc_batch(x, W_enc, b_enc, hA, sB, t + 16, bid, tid);
        if (t + 1 < TT)
            xz_phase(W_x, b_lstm, hA, sB, xzP[(t + 1) & 1], t + 1, m0, j0, tid);

        const float* hb = g_hbuf[t & 1];
        float* hn = g_hbuf[(t + 1) & 1];
        float* zS = xzP[t & 1];

        // acc init from this block's xz slice (each thread reads its own cells)
        float acc[8][4];
#pragma unroll
        for (int i = 0; i < 8; i++)
#pragma unroll
            for (int j = 0; j < 4; j++)
                acc[i][j] = zS[(tm * 8 + i) * 65 + tn * 4 + j];

        // z += h_prev @ Ws   (K = 512, chunks of 16)
#pragma unroll 1
        for (int kc = 0; kc < DLAT; kc += 16) {
#pragma unroll
            for (int q2 = 0; q2 < 2; q2++) {
                int f = tid * 2 + q2;
                int m = f >> 2, qq = f & 3;
                float4 v = *reinterpret_cast<const float4*>(&hb[(m0 + m) * DLAT + kc + qq * 4]);
                hA[(qq * 4 + 0) * 68 + m] = v.x; hA[(qq * 4 + 1) * 68 + m] = v.y;
                hA[(qq * 4 + 2) * 68 + m] = v.z; hA[(qq * 4 + 3) * 68 + m] = v.w;
            }
            __syncthreads();
#pragma unroll
            for (int k = 0; k < 16; k++) {
                float a[8], b[4];
                *reinterpret_cast<float4*>(&a[0]) = *reinterpret_cast<const float4*>(&hA[k * 68 + tm * 8]);
                *reinterpret_cast<float4*>(&a[4]) = *reinterpret_cast<const float4*>(&hA[k * 68 + tm * 8 + 4]);
                *reinterpret_cast<float4*>(&b[0]) = *reinterpret_cast<const float4*>(&Ws[(kc + k) * 64 + tn * 4]);
#pragma unroll
                for (int i = 0; i < 8; i++)
#pragma unroll
                    for (int j = 0; j < 4; j++) acc[i][j] = fmaf(a[i], b[j], acc[i][j]);
            }
            __syncthreads();
        }

        // stage z back into the (now-consumed) xz slot for gate-gather
#pragma unroll
        for (int i = 0; i < 8; i++)
#pragma unroll
            for (int j = 0; j < 4; j++)
                zS[(tm * 8 + i) * 65 + tn * 4 + j] = acc[i][j];
        __syncthreads();

        // gates + state update: 1024 cells / 128 threads
#pragma unroll
        for (int it = 0; it < 8; it++) {
            int m = (tid >> 4) + it * 8;
            int j = tid & 15;
            float zi = zS[m * 65 + j];
            float zf = zS[m * 65 + 16 + j];
            float zg = zS[m * 65 + 32 + j];
            float zo = zS[m * 65 + 48 + j];
            float ig = sigmoidf_(zi);
            float fg = sigmoidf_(zf);
            float gg = tanhf_(zg);
            float og = sigmoidf_(zo);
            float cn = fg * cS[m * 16 + j] + ig * gg;
            cS[m * 16 + j] = cn;
            hn[(m0 + m) * DLAT + j0 + j] = og * tanhf_(cn);
        }
        grid_sync(&gen);
    }

    // decoder: out[b] = h_last @ W_dec + b_dec  (h_last in buf[TT&1] = buf[0])
    if (jb == 0 && tid < 64) {
        int row = m0 + tid;
        const float* hf = g_hbuf[0];
        float s = 0.0f;
        for (int k = 0; k < DLAT; k++) s = fmaf(hf[row * DLAT + k], W_dec[k], s);
        out[row] = s + b_dec[0];
    }
}

// ---------------- eager touch (harmless; materializes module early if possible) ----
namespace {
struct EagerLoad {
    EagerLoad() {
        void* p;
        cudaGetSymbolAddress(&p, g_encbuf);
        cudaGetSymbolAddress(&p, g_hbuf);
        cudaGetSymbolAddress(&p, g_bar_cnt);
        cudaGetSymbolAddress(&p, g_bar_gen);
        cudaFuncSetAttribute(lstm_fused_kernel,
                             cudaFuncAttributeMaxDynamicSharedMemorySize,
                             SMEM_FLOATS * (int)sizeof(float));
    }
};
EagerLoad eager_load_instance;
}  // namespace

// ---------------- launch ----------------
extern "C" void kernel_launch(void* const* d_in, const int* in_sizes, int n_in,
                              void* d_out, int out_size)
{
    const float* x      = (const float*)d_in[0];
    const float* W_enc  = (const float*)d_in[1];
    const float* b_enc  = (const float*)d_in[2];
    const float* W_x    = (const float*)d_in[3];
    const float* W_h    = (const float*)d_in[4];
    const float* b_lstm = (const float*)d_in[5];
    const float* W_dec  = (const float*)d_in[6];
    const float* b_dec  = (const float*)d_in[7];
    float* out = (float*)d_out;

    cudaFuncSetAttribute(lstm_fused_kernel,
                         cudaFuncAttributeMaxDynamicSharedMemorySize,
                         SMEM_FLOATS * (int)sizeof(float));

    lstm_fused_kernel<<<NBLK, 128, SMEM_FLOATS * (int)sizeof(float)>>>(
        x, W_enc, b_enc, W_x, W_h, b_lstm, W_dec, b_dec, out);
}

// round 6
// speedup vs baseline: 2.2159x; 2.2132x over previous
#include <cuda_runtime.h>
#include <cuda_bf16.h>
#include <cstdint>

// Problem constants
#define BATCH 256
#define TT    512
#define DIN   128
#define DFEAT 256
#define DLAT  512
#define GG    2048
#define NBLK  128            // 4 batch-tiles x 32 gate-tiles, persistent, 1 CTA/SM
#define NTHR  128
#define ENC_SLOTS 32

// ---------------- device-global scratch (~9 MB) ----------------
__device__ __nv_bfloat16 g_enchi[ENC_SLOTS][BATCH * DFEAT];  // 4 MB
__device__ __nv_bfloat16 g_enclo[ENC_SLOTS][BATCH * DFEAT];  // 4 MB
__device__ __nv_bfloat16 g_hhi[2][BATCH * DLAT];             // .5 MB
__device__ __nv_bfloat16 g_hlo[2][BATCH * DLAT];             // .5 MB
__device__ unsigned g_bar_cnt;
__device__ unsigned g_bar_gen;

// ---------------- smem layout (bytes) ----------------
#define SM_WHI  0                        // W_h hi  [64 n][512 k] bf16, row=1024B
#define SM_WLO  65536
#define SM_XHI  131072                   // W_x hi  [64 n][256 k] bf16, row=512B
#define SM_XLO  163840
#define SM_ENC  196608                   // enc staging: hA 16*68 f32 + sB 16*64 f32
#define SM_BIAS (SM_ENC + 8448)          // 64 floats
#define SM_TOTAL (SM_BIAS + 256)         // 205,312 B

// ---------------- math ----------------
__device__ __forceinline__ float sigmoidf_(float x) { return 1.0f / (1.0f + __expf(-x)); }
__device__ __forceinline__ float tanhf_(float x) {
    x = fminf(fmaxf(x, -12.0f), 12.0f);
    float e = __expf(2.0f * x);
    return (e - 1.0f) / (e + 1.0f);
}

// ---------------- grid barrier (128 co-resident CTAs) ----------------
__device__ __forceinline__ void grid_sync(unsigned* gen) {
    __syncthreads();
    if (threadIdx.x == 0) {
        __threadfence();
        unsigned arrived = atomicAdd(&g_bar_cnt, 1u);
        if (arrived == NBLK - 1) {
            atomicExch(&g_bar_cnt, 0u);
            __threadfence();
            *((volatile unsigned*)&g_bar_gen) = *gen + 1u;
        } else {
            while (*((volatile unsigned*)&g_bar_gen) == *gen) { __nanosleep(64); }
        }
        __threadfence();
    }
    __syncthreads();
    (*gen)++;
}

// ---------------- PTX helpers (baseline PTX only: sm_80-era, valid for sm_100) --
__device__ __forceinline__ uint32_t s2u(const void* p) {
    uint32_t a;
    asm("{ .reg .u64 t; cvta.to.shared.u64 t, %1; cvt.u32.u64 %0, t; }" : "=r"(a) : "l"(p));
    return a;
}
__device__ __forceinline__ void ldsm4(uint32_t& r0, uint32_t& r1, uint32_t& r2, uint32_t& r3,
                                      uint32_t addr) {
    asm volatile("ldmatrix.sync.aligned.m8n8.x4.shared.b16 {%0,%1,%2,%3}, [%4];"
                 : "=r"(r0), "=r"(r1), "=r"(r2), "=r"(r3) : "r"(addr));
}
__device__ __forceinline__ void mma4(float* d, const uint32_t* a, const uint32_t* b) {
    asm volatile(
        "mma.sync.aligned.m16n8k16.row.col.f32.bf16.bf16.f32 "
        "{%0,%1,%2,%3}, {%4,%5,%6,%7}, {%8,%9}, {%0,%1,%2,%3};"
        : "+f"(d[0]), "+f"(d[1]), "+f"(d[2]), "+f"(d[3])
        : "r"(a[0]), "r"(a[1]), "r"(a[2]), "r"(a[3]), "r"(b[0]), "r"(b[1]));
}

// ---------------- hi/lo split helper ----------------
__device__ __forceinline__ void split_bf16(float v, unsigned short& hi, unsigned short& lo) {
    __nv_bfloat16 h16 = __float2bfloat16(v);
    __nv_bfloat16 l16 = __float2bfloat16(v - __bfloat162float(h16));
    hi = __bfloat16_as_ushort(h16);
    lo = __bfloat16_as_ushort(l16);
}

// ---------------- MMA accumulate: acc += A(global,hi/lo) @ B(smem,hi/lo) -------
// A: this thread's fragment rows r0,r0+8 at byte base aHiT/aLoT (incl. lane col
// offset), row stride RS bytes. B: per-lane ldmatrix base addrs (4 pair-calls).
// NCH k-chunks of 16. 3-pass: AhiBhi + AhiBlo + AloBhi.
template<int NCH, int RS>
__device__ __forceinline__ void mma_acc(
    float (&acc)[8][4],
    const char* aHiT, const char* aLoT,
    const uint32_t* bHiA, const uint32_t* bLoA,
    int koff, int swz)
{
    uint32_t aH[4], aL[4], aHn[4], aLn[4];
#pragma unroll
    for (int i = 0; i < 4; i++) {
        int ofs = (i & 1) * 8 * RS + (i >> 1) * 16;
        aH[i] = *(const uint32_t*)(aHiT + ofs);
        aL[i] = *(const uint32_t*)(aLoT + ofs);
    }
#pragma unroll 1
    for (int c = 0; c < NCH; c++) {
        const int kb = c * 32;                       // bytes = 2*kc
        if (c + 1 < NCH) {                           // distance-1 A prefetch
#pragma unroll
            for (int i = 0; i < 4; i++) {
                int ofs = kb + 32 + (i & 1) * 8 * RS + (i >> 1) * 16;
                aHn[i] = *(const uint32_t*)(aHiT + ofs);
                aLn[i] = *(const uint32_t*)(aLoT + ofs);
            }
        }
        uint32_t bh[8][2], bl[8][2];
        const int off = (kb + koff) ^ swz;
#pragma unroll
        for (int p = 0; p < 4; p++) {
            ldsm4(bh[2 * p][0], bh[2 * p][1], bh[2 * p + 1][0], bh[2 * p + 1][1], bHiA[p] + off);
            ldsm4(bl[2 * p][0], bl[2 * p][1], bl[2 * p + 1][0], bl[2 * p + 1][1], bLoA[p] + off);
        }
#pragma unroll
        for (int nt = 0; nt < 8; nt++) {
            mma4(acc[nt], aH, bh[nt]);
            mma4(acc[nt], aH, bl[nt]);
            mma4(acc[nt], aL, bh[nt]);
        }
#pragma unroll
        for (int i = 0; i < 4; i++) { aH[i] = aHn[i]; aL[i] = aLn[i]; }
    }
}

// ---------------- encoder FFMA phase (amortized /8 steps) ----------------
// 128 CTAs cover 8 timesteps x 4 batch-tiles x 4 col-tiles of 64.
__device__ void enc_phase(
    char* smem, const float* __restrict__ x, const float* __restrict__ W_enc,
    const float* __restrict__ b_enc, int sbase, int bid, int tid)
{
    const int q = bid >> 2;
    const int s = sbase + (q >> 2);
    if (s >= TT) return;
    const int b0  = (q & 3) * 64;
    const int n0e = (bid & 3) * 64;
    const int tn = tid & 15, tm = tid >> 4;
    float* hA = reinterpret_cast<float*>(smem + SM_ENC);         // [16][68]
    float* sB = hA + 16 * 68;                                    // [16][64]

    float acc[8][4];
#pragma unroll
    for (int i = 0; i < 8; i++)
#pragma unroll
        for (int j = 0; j < 4; j++) acc[i][j] = 0.0f;

#pragma unroll 1
    for (int k0 = 0; k0 < DIN; k0 += 16) {
#pragma unroll
        for (int q2 = 0; q2 < 2; q2++) {              // A^T: 256 float4
            int f = tid * 2 + q2;
            int row = f >> 2, kq = f & 3;
            float4 v = *reinterpret_cast<const float4*>(
                &x[(size_t)(b0 + row) * TT * DIN + (size_t)s * DIN + k0 + kq * 4]);
            hA[(kq * 4 + 0) * 68 + row] = v.x; hA[(kq * 4 + 1) * 68 + row] = v.y;
            hA[(kq * 4 + 2) * 68 + row] = v.z; hA[(kq * 4 + 3) * 68 + row] = v.w;
        }
#pragma unroll
        for (int q2 = 0; q2 < 2; q2++) {              // B: 256 float4
            int f = tid * 2 + q2;
            int kr = f >> 4, nq = f & 15;
            float4 v = *reinterpret_cast<const float4*>(
                &W_enc[(size_t)(k0 + kr) * DFEAT + n0e + nq * 4]);
            *reinterpret_cast<float4*>(&sB[kr * 64 + nq * 4]) = v;
        }
        __syncthreads();
#pragma unroll
        for (int k = 0; k < 16; k++) {
            float a[8], b[4];
            *reinterpret_cast<float4*>(&a[0]) = *reinterpret_cast<const float4*>(&hA[k * 68 + tm * 8]);
            *reinterpret_cast<float4*>(&a[4]) = *reinterpret_cast<const float4*>(&hA[k * 68 + tm * 8 + 4]);
            *reinterpret_cast<float4*>(&b[0]) = *reinterpret_cast<const float4*>(&sB[k * 64 + tn * 4]);
#pragma unroll
            for (int i = 0; i < 8; i++)
#pragma unroll
                for (int j = 0; j < 4; j++) acc[i][j] = fmaf(a[i], b[j], acc[i][j]);
        }
        __syncthreads();
    }

    float bia[4];
    *reinterpret_cast<float4*>(&bia[0]) = *reinterpret_cast<const float4*>(&b_enc[n0e + tn * 4]);
    __nv_bfloat16* dhi = g_enchi[s & (ENC_SLOTS - 1)];
    __nv_bfloat16* dlo = g_enclo[s & (ENC_SLOTS - 1)];
#pragma unroll
    for (int i = 0; i < 8; i++) {
        unsigned uh[2] = {0, 0}, ul[2] = {0, 0};
#pragma unroll
        for (int j = 0; j < 4; j++) {
            float v = tanhf_(acc[i][j] + bia[j]);
            unsigned short sh, sl;
            split_bf16(v, sh, sl);
            uh[j >> 1] |= (unsigned)sh << ((j & 1) * 16);
            ul[j >> 1] |= (unsigned)sl << ((j & 1) * 16);
        }
        size_t off = (size_t)(b0 + tm * 8 + i) * DFEAT + n0e + tn * 4;
        *reinterpret_cast<uint2*>(dhi + off) = make_uint2(uh[0], uh[1]);
        *reinterpret_cast<uint2*>(dlo + off) = make_uint2(ul[0], ul[1]);
    }
}

// ---------------- the fused persistent HMMA kernel ----------------
__global__ void __launch_bounds__(NTHR, 1) lstm_hmma_kernel(
    const float* __restrict__ x, const float* __restrict__ W_enc,
    const float* __restrict__ b_enc, const float* __restrict__ W_x,
    const float* __restrict__ W_h, const float* __restrict__ b_lstm,
    const float* __restrict__ W_dec, const float* __restrict__ b_dec,
    float* __restrict__ out)
{
    extern __shared__ char smem[];
    const int tid = threadIdx.x;
    const int bid = blockIdx.x;
    const int lane = tid & 31;
    const int wid = tid >> 5;
    const int jb = bid & 31;             // gate tile (16 latent cols)
    const int mb = bid >> 5;             // batch tile (64 rows)
    const int m0 = mb * 64, j0 = jb * 16;
    const uint32_t smem_u = s2u(smem);
    float* biasS = reinterpret_cast<float*>(smem + SM_BIAS);

    // ---- fill weight slices (bf16 hi/lo, [n][k] rows, XOR-swizzled) ----
    for (int idx = tid; idx < 64 * 512; idx += NTHR) {
        int n = idx >> 9, k = idx & 511;
        float w = W_h[(size_t)k * GG + (n >> 4) * DLAT + j0 + (n & 15)];
        unsigned short sh, sl;
        split_bf16(w, sh, sl);
        uint32_t off = (uint32_t)(n * 1024 + ((2 * k) ^ ((n & 7) << 4)));
        *reinterpret_cast<unsigned short*>(smem + SM_WHI + off) = sh;
        *reinterpret_cast<unsigned short*>(smem + SM_WLO + off) = sl;
    }
    for (int idx = tid; idx < 64 * 256; idx += NTHR) {
        int n = idx >> 8, k = idx & 255;
        float w = W_x[(size_t)k * GG + (n >> 4) * DLAT + j0 + (n & 15)];
        unsigned short sh, sl;
        split_bf16(w, sh, sl);
        uint32_t off = (uint32_t)(n * 512 + ((2 * k) ^ ((n & 7) << 4)));
        *reinterpret_cast<unsigned short*>(smem + SM_XHI + off) = sh;
        *reinterpret_cast<unsigned short*>(smem + SM_XLO + off) = sl;
    }
    if (tid < 64) biasS[tid] = b_lstm[(tid >> 4) * DLAT + j0 + (tid & 15)];

    // ---- per-lane fragment geometry ----
    const int r0 = m0 + wid * 16 + (lane >> 2);        // A-frag row (and row+8)
    const int acol = 4 * (lane & 3);                   // A-frag k byte offset
    const int lm = lane >> 3, lr = lane & 7;
    const int koff = (lm & 1) * 16;                    // B klow/khigh select
    const int swz = lr << 4;                           // B swizzle
    uint32_t bW_hi[4], bW_lo[4], bX_hi[4], bX_lo[4];
#pragma unroll
    for (int p = 0; p < 4; p++) {
        int n = 16 * p + 8 * (lm >> 1) + lr;
        bW_hi[p] = smem_u + SM_WHI + n * 1024;
        bW_lo[p] = smem_u + SM_WLO + n * 1024;
        bX_hi[p] = smem_u + SM_XHI + n * 512;
        bX_lo[p] = smem_u + SM_XLO + n * 512;
    }
    const int jc = 2 * (lane & 3);

    unsigned gen = *((volatile unsigned*)&g_bar_gen);
    float cReg[8];
#pragma unroll
    for (int i = 0; i < 8; i++) cReg[i] = 0.0f;
    float acc[8][4];

    // ---- prologue: enc slots [0,16); xz(0) ----
    __syncthreads();                                   // weights/bias visible
    enc_phase(smem, x, W_enc, b_enc, 0, bid, tid);
    enc_phase(smem, x, W_enc, b_enc, 8, bid, tid);
    grid_sync(&gen);
#pragma unroll
    for (int i = 0; i < 8; i++)
#pragma unroll
        for (int j = 0; j < 4; j++) acc[i][j] = 0.0f;
    mma_acc<16, 512>(acc,
        (const char*)g_enchi[0] + (size_t)r0 * 512 + acol,
        (const char*)g_enclo[0] + (size_t)r0 * 512 + acol,
        bX_hi, bX_lo, koff, swz);

    // ---- main scan ----
#pragma unroll 1
    for (int t = 0; t < TT; t++) {
        // recurrent: acc += h(t) @ W_h   (skip t=0: h(0)=0)
        if (t > 0) {
            mma_acc<32, 1024>(acc,
                (const char*)g_hhi[t & 1] + (size_t)r0 * 1024 + acol,
                (const char*)g_hlo[t & 1] + (size_t)r0 * 1024 + acol,
                bW_hi, bW_lo, koff, swz);
        }

        // epilogue: gates -> c,h(t+1)
        __nv_bfloat16* ohh = g_hhi[(t + 1) & 1];
        __nv_bfloat16* ohl = g_hlo[(t + 1) & 1];
#pragma unroll
        for (int rs = 0; rs < 2; rs++) {
            const int row = r0 + 8 * rs;
#pragma unroll
            for (int jhi = 0; jhi < 2; jhi++) {
                uint32_t packH = 0, packL = 0;
#pragma unroll
                for (int je = 0; je < 2; je++) {
                    const int j = 8 * jhi + jc + je;
                    float zi = acc[0 + jhi][2 * rs + je] + biasS[j];
                    float zf = acc[2 + jhi][2 * rs + je] + biasS[16 + j];
                    float zg = acc[4 + jhi][2 * rs + je] + biasS[32 + j];
                    float zo = acc[6 + jhi][2 * rs + je] + biasS[48 + j];
                    float ig = sigmoidf_(zi), fg = sigmoidf_(zf);
                    float gg = tanhf_(zg),   og = sigmoidf_(zo);
                    const int ci = rs * 4 + jhi * 2 + je;
                    float cn = fg * cReg[ci] + ig * gg;
                    cReg[ci] = cn;
                    float hv = og * tanhf_(cn);
                    unsigned short sh, sl;
                    split_bf16(hv, sh, sl);
                    packH |= (uint32_t)sh << (16 * je);
                    packL |= (uint32_t)sl << (16 * je);
                }
                size_t o = (size_t)row * DLAT + j0 + 8 * jhi + jc;
                *reinterpret_cast<uint32_t*>(ohh + o) = packH;
                *reinterpret_cast<uint32_t*>(ohl + o) = packL;
            }
        }

        // encoder lookahead (acc is dead here; only cReg live)
        if ((t & 7) == 0 && t + 16 < TT)
            enc_phase(smem, x, W_enc, b_enc, t + 16, bid, tid);

        grid_sync(&gen);                               // publish h(t+1)

        // xz(t+1) into acc
        if (t + 1 < TT) {
            const int slot = (t + 1) & (ENC_SLOTS - 1);
#pragma unroll
            for (int i = 0; i < 8; i++)
#pragma unroll
                for (int j = 0; j < 4; j++) acc[i][j] = 0.0f;
            mma_acc<16, 512>(acc,
                (const char*)g_enchi[slot] + (size_t)r0 * 512 + acol,
                (const char*)g_enclo[slot] + (size_t)r0 * 512 + acol,
                bX_hi, bX_lo, koff, swz);
        }
    }

    // ---- decoder: out[b] = h_last @ W_dec + b_dec (h_last in buf 0) ----
    if (jb == 0 && tid < 64) {
        int row = m0 + tid;
        const __nv_bfloat16* hh = g_hhi[0];
        const __nv_bfloat16* hl = g_hlo[0];
        float s = 0.0f;
        for (int k = 0; k < DLAT; k++) {
            float hv = __bfloat162float(hh[(size_t)row * DLAT + k]) +
                       __bfloat162float(hl[(size_t)row * DLAT + k]);
            s = fmaf(hv, W_dec[k], s);
        }
        out[row] = s + b_dec[0];
    }
}

// ---------------- eager module touch ----------------
namespace {
struct EagerLoad {
    EagerLoad() {
        void* p;
        cudaGetSymbolAddress(&p, g_enchi);
        cudaGetSymbolAddress(&p, g_hhi);
        cudaGetSymbolAddress(&p, g_bar_cnt);
        cudaFuncSetAttribute(lstm_hmma_kernel,
                             cudaFuncAttributeMaxDynamicSharedMemorySize, SM_TOTAL);
    }
};
EagerLoad eager_load_instance;
}  // namespace

// ---------------- launch ----------------
extern "C" void kernel_launch(void* const* d_in, const int* in_sizes, int n_in,
                              void* d_out, int out_size)
{
    const float* x      = (const float*)d_in[0];
    const float* W_enc  = (const float*)d_in[1];
    const float* b_enc  = (const float*)d_in[2];
    const float* W_x    = (const float*)d_in[3];
    const float* W_h    = (const float*)d_in[4];
    const float* b_lstm = (const float*)d_in[5];
    const float* W_dec  = (const float*)d_in[6];
    const float* b_dec  = (const float*)d_in[7];
    float* out = (float*)d_out;

    cudaFuncSetAttribute(lstm_hmma_kernel,
                         cudaFuncAttributeMaxDynamicSharedMemorySize, SM_TOTAL);

    lstm_hmma_kernel<<<NBLK, NTHR, SM_TOTAL>>>(
        x, W_enc, b_enc, W_x, W_h, b_lstm, W_dec, b_dec, out);
}